// round 10
// baseline (speedup 1.0000x reference)
#include <cuda_runtime.h>
#include <cuda_bf16.h>
#include <cstdint>

// ---------------- problem constants ----------------
#define NTOK   16384
#define HIN    768
#define NPACK  1536      // grouped gate cols: 16 groups x 96 (= i|g|o x 32 j)
#define HIDC   512
#define NTAG   20
#define NCHUNK 128
#define CLEN   128
#define NEGV   (-10000.0f)

// ---------------- device scratch ----------------
__device__ __nv_bfloat16 d_Ahi[(size_t)NTOK * HIN];
__device__ __nv_bfloat16 d_Alo[(size_t)NTOK * HIN];
__device__ __nv_bfloat16 d_Bhi[(size_t)NPACK * HIN];   // grouped rows, K-major
__device__ __nv_bfloat16 d_Blo[(size_t)NPACK * HIN];
__device__ float d_biasG[NPACK];
__device__ float d_enc[(size_t)NTOK * HIDC];
__device__ float d_feats[NTOK * NTAG];
__device__ float d_P[NCHUNK * NTAG * NTAG];
__device__ float d_fvs[NCHUNK * NTAG];
__device__ float d_finalfv[NTAG];
__device__ unsigned char d_bps[NTOK * NTAG];
__device__ unsigned char d_Wc[NCHUNK * NTAG];
__device__ unsigned char d_r[NCHUNK];

// ---------------- helpers ----------------
__device__ __forceinline__ uint32_t smem_u32(const void* p) {
    uint32_t a;
    asm("{ .reg .u64 t; cvta.to.shared.u64 t, %1; cvt.u32.u64 %0, t; }" : "=r"(a) : "l"(p));
    return a;
}
#define CP_ASYNC16(dst, src) \
    asm volatile("cp.async.cg.shared.global [%0], [%1], 16;" :: "r"(dst), "l"(src))
#define CP_COMMIT() asm volatile("cp.async.commit_group;" ::: "memory")
#define CP_WAIT(n)  asm volatile("cp.async.wait_group %0;" :: "n"(n) : "memory")

__device__ __forceinline__ void ldm_x4(uint32_t* r, uint32_t addr) {
    asm volatile("ldmatrix.sync.aligned.m8n8.x4.shared.b16 {%0,%1,%2,%3}, [%4];"
                 : "=r"(r[0]), "=r"(r[1]), "=r"(r[2]), "=r"(r[3]) : "r"(addr));
}
__device__ __forceinline__ void mma16816(float* c, const uint32_t* a, uint32_t b0, uint32_t b1) {
    asm volatile(
        "mma.sync.aligned.m16n8k16.row.col.f32.bf16.bf16.f32 "
        "{%0,%1,%2,%3}, {%4,%5,%6,%7}, {%8,%9}, {%0,%1,%2,%3};"
        : "+f"(c[0]), "+f"(c[1]), "+f"(c[2]), "+f"(c[3])
        : "r"(a[0]), "r"(a[1]), "r"(a[2]), "r"(a[3]), "r"(b0), "r"(b1));
}
__device__ __forceinline__ void split2(float f, __nv_bfloat16& h, __nv_bfloat16& l) {
    h = __float2bfloat16_rn(f);
    l = __float2bfloat16_rn(f - __bfloat162float(h));
}

// ---------------- K0: merged input split + weight pack ----------------
#define XBLK ((NTOK * HIN / 4) / 256)     // 12288
#define WBLK ((NPACK * HIN / 4) / 256)    // 1152
__global__ void prep_kernel(const float* __restrict__ x,
                            const float* __restrict__ wf, const float* __restrict__ wb,
                            const float* __restrict__ bihf, const float* __restrict__ bhhf,
                            const float* __restrict__ bihb, const float* __restrict__ bhhb) {
    int b = blockIdx.x;
    if (b < XBLK) {
        int idx = b * 256 + threadIdx.x;
        float4 v = *(const float4*)(x + HIN + (size_t)idx * 4);  // skip token 0
        float f[4] = {v.x, v.y, v.z, v.w};
        __nv_bfloat16 hi[4], lo[4];
#pragma unroll
        for (int i = 0; i < 4; i++) split2(f[i], hi[i], lo[i]);
        *(ulonglong1*)(d_Ahi + (size_t)idx * 4) = *(ulonglong1*)hi;
        *(ulonglong1*)(d_Alo + (size_t)idx * 4) = *(ulonglong1*)lo;
    } else {
        int idx = (b - XBLK) * 256 + threadIdx.x;
        int n = idx / (HIN / 4);
        int kq = (idx % (HIN / 4)) * 4;
        int g = n / 96, cg = n % 96;
        int dir = g >> 3, jblk = g & 7;
        int gate = cg / 32, jj = cg % 32;
        int gateoff = (gate == 0) ? 0 : (gate == 1 ? 512 : 768);
        int r = gateoff + jblk * 32 + jj;
        const float* w = dir ? wb : wf;
        float4 v = *(const float4*)(w + (size_t)r * HIN + kq);
        float f[4] = {v.x, v.y, v.z, v.w};
        __nv_bfloat16 hi[4], lo[4];
#pragma unroll
        for (int i = 0; i < 4; i++) split2(f[i], hi[i], lo[i]);
        *(ulonglong1*)(d_Bhi + (size_t)n * HIN + kq) = *(ulonglong1*)hi;
        *(ulonglong1*)(d_Blo + (size_t)n * HIN + kq) = *(ulonglong1*)lo;
        if (kq == 0) {
            const float* bih = dir ? bihb : bihf;
            const float* bhh = dir ? bhhb : bhhf;
            d_biasG[n] = bih[r] + bhh[r];
        }
    }
}

// ---------------- K1: fused bf16 mma GEMM (3-term split) + LSTM activation ----------------
// CTA tile 128x96, 256 threads, 8 warps (warp tile 32x48), 2 CTAs/SM
#define BKE 32
#define ASTR 40
#define NKI 72                    // 3 passes x 24 k-tiles of 32 over K=768
#define SA_STAGE (128 * ASTR)
#define SB_STAGE (96 * ASTR)
#define GSMEM ((4 * SA_STAGE + 4 * SB_STAGE) * 2)   // 71680 B
#define EXSTR 100

// phase q = kt/24: 0:(Ahi,Bhi) 1:(Ahi,Blo) 2:(Alo,Bhi); offset (kt%24)*32
#define KSRC(kt, pa, pb)                                                        \
    do {                                                                        \
        int q_ = (kt) / 24, off_ = ((kt) % 24) * BKE;                           \
        pa = (q_ == 2 ? d_Alo : d_Ahi) + (size_t)(bm * 128) * HIN + off_;       \
        pb = (q_ == 1 ? d_Blo : d_Bhi) + (size_t)(g * 96) * HIN + off_;         \
    } while (0)

__global__ __launch_bounds__(256, 2) void gemm_fused() {
    extern __shared__ char dsm[];
    __nv_bfloat16* Asm = (__nv_bfloat16*)dsm;
    __nv_bfloat16* Bsm = Asm + 4 * SA_STAGE;
    float* Ex = (float*)dsm;                 // epilogue overlay: 64 x EXSTR fp32
    int tid = threadIdx.x;
    int wid = tid >> 5, lane = tid & 31;
    int wm = wid >> 1, wn = wid & 1;         // warp tile 32 x 48 (wm 0..3, wn 0..1)
    int g = blockIdx.x, bm = blockIdx.y;

    uint32_t sA = smem_u32(Asm), sB = smem_u32(Bsm);

    float acc[2][6][4];
#pragma unroll
    for (int i = 0; i < 2; i++)
#pragma unroll
        for (int j = 0; j < 6; j++)
#pragma unroll
            for (int q = 0; q < 4; q++) acc[i][j][q] = 0.f;

#define LOAD_STAGE(s, pa, pb)                                                            \
    do {                                                                                 \
        _Pragma("unroll")                                                                \
        for (int i_ = 0; i_ < 2; i_++) {                                                 \
            int c_ = tid + i_ * 256;                                                     \
            int row_ = c_ >> 2, seg_ = c_ & 3;                                           \
            CP_ASYNC16(sA + (uint32_t)(((s) * SA_STAGE + row_ * ASTR + seg_ * 8) * 2),   \
                       (pa) + (size_t)row_ * HIN + seg_ * 8);                            \
        }                                                                                \
        _Pragma("unroll")                                                                \
        for (int i_ = 0; i_ < 2; i_++) {                                                 \
            int c_ = tid + i_ * 256;                                                     \
            if (c_ < 384) {                                                              \
                int row_ = c_ >> 2, seg_ = c_ & 3;                                       \
                CP_ASYNC16(sB + (uint32_t)(((s) * SB_STAGE + row_ * ASTR + seg_ * 8) * 2), \
                           (pb) + (size_t)row_ * HIN + seg_ * 8);                        \
            }                                                                            \
        }                                                                                \
    } while (0)

    {
        const __nv_bfloat16 *pa, *pb;
        KSRC(0, pa, pb); LOAD_STAGE(0, pa, pb); CP_COMMIT();
        KSRC(1, pa, pb); LOAD_STAGE(1, pa, pb); CP_COMMIT();
        KSRC(2, pa, pb); LOAD_STAGE(2, pa, pb); CP_COMMIT();
    }

    for (int kt = 0; kt < NKI; kt++) {
        if (kt < NKI - 2) { CP_WAIT(2); }
        else if (kt == NKI - 2) { CP_WAIT(1); }
        else { CP_WAIT(0); }
        __syncthreads();
        int cs = kt & 3;

#pragma unroll
        for (int ks = 0; ks < 2; ks++) {
            int k0 = ks * 16;
            uint32_t afr[2][4];
#pragma unroll
            for (int i = 0; i < 2; i++) {
                int row = wm * 32 + i * 16 + (lane & 15);
                uint32_t addr = sA + (uint32_t)((cs * SA_STAGE + row * ASTR + k0 + ((lane >> 4) * 8)) * 2);
                ldm_x4(afr[i], addr);
            }
            uint32_t bfr[3][4];
#pragma unroll
            for (int p = 0; p < 3; p++) {
                int row = wn * 48 + p * 16 + (lane & 15);
                uint32_t addr = sB + (uint32_t)((cs * SB_STAGE + row * ASTR + k0 + ((lane >> 4) * 8)) * 2);
                ldm_x4(bfr[p], addr);
            }
#pragma unroll
            for (int i = 0; i < 2; i++)
#pragma unroll
                for (int p = 0; p < 3; p++) {
                    mma16816(acc[i][2 * p + 0], afr[i], bfr[p][0], bfr[p][2]);
                    mma16816(acc[i][2 * p + 1], afr[i], bfr[p][1], bfr[p][3]);
                }
        }

        if (kt + 3 < NKI) {
            const __nv_bfloat16 *pa, *pb;
            KSRC(kt + 3, pa, pb);
            LOAD_STAGE((kt + 3) & 3, pa, pb);
            CP_COMMIT();
        }
    }
    __syncthreads();

    // ---- fused epilogue: bias + LSTM activation -> enc ----
    float2 bias[6];
#pragma unroll
    for (int jt = 0; jt < 6; jt++) {
        int col = g * 96 + wn * 48 + jt * 8 + (lane & 3) * 2;
        bias[jt] = *(const float2*)(d_biasG + col);
    }
    int dir = g >> 3, jblk = g & 7;
    int base = dir * 256 + jblk * 32;

#pragma unroll
    for (int ch = 0; ch < 2; ch++) {
        if ((wm >> 1) == ch) {
#pragma unroll
            for (int i = 0; i < 2; i++) {
                int r = (wm & 1) * 32 + i * 16 + (lane >> 2);
                int cbase = wn * 48 + (lane & 3) * 2;
#pragma unroll
                for (int jt = 0; jt < 6; jt++) {
                    int c = cbase + jt * 8;
                    Ex[r * EXSTR + c]           = acc[i][jt][0] + bias[jt].x;
                    Ex[r * EXSTR + c + 1]       = acc[i][jt][1] + bias[jt].y;
                    Ex[(r + 8) * EXSTR + c]     = acc[i][jt][2] + bias[jt].x;
                    Ex[(r + 8) * EXSTR + c + 1] = acc[i][jt][3] + bias[jt].y;
                }
            }
        }
        __syncthreads();
        // 64 rows x 32 j outputs = 2048 -> 8 iters of 256 threads
#pragma unroll
        for (int u = 0; u < 8; u++) {
            int idx = u * 256 + tid;
            int r = idx >> 5, j = idx & 31;
            float iv = Ex[r * EXSTR + j];
            float gv = Ex[r * EXSTR + 32 + j];
            float ov = Ex[r * EXSTR + 64 + j];
            float si = 1.f / (1.f + expf(-iv));
            float cc = si * tanhf(gv);
            float so = 1.f / (1.f + expf(-ov));
            d_enc[(size_t)(bm * 128 + ch * 64 + r) * HIDC + base + j] = so * tanhf(cc);
        }
        __syncthreads();
    }
}

// ---------------- K3: feats = enc @ w_tag^T + b_tag ----------------
#define FT_TOK 32
__global__ __launch_bounds__(256) void feats_kernel(const float* __restrict__ wtag,
                                                    const float* __restrict__ btag) {
    extern __shared__ float esm[];   // [FT_TOK][HIDC] = 64KB
    int warp = threadIdx.x >> 5, lane = threadIdx.x & 31;
    int tw = warp & 3, half = warp >> 2;
    float wreg[5][16];
#pragma unroll
    for (int t = 0; t < 5; t++)
#pragma unroll
        for (int q = 0; q < 16; q++)
            wreg[t][q] = wtag[(tw * 5 + t) * HIDC + q * 32 + lane];
    float bloc[5];
#pragma unroll
    for (int t = 0; t < 5; t++) bloc[t] = btag[tw * 5 + t];

    int tok0 = blockIdx.x * FT_TOK;
    const float4* src = (const float4*)(d_enc + (size_t)tok0 * HIDC);
    float4* dst = (float4*)esm;
    for (int i = threadIdx.x; i < FT_TOK * HIDC / 4; i += 256) dst[i] = src[i];
    __syncthreads();

    // two tokens in flight -> interleaved shfl chains
    for (int tk = 0; tk < 8; tk++) {
        int tokA = half * 16 + tk;
        int tokB = tokA + 8;
        float sA[5] = {0.f, 0.f, 0.f, 0.f, 0.f};
        float sB[5] = {0.f, 0.f, 0.f, 0.f, 0.f};
#pragma unroll
        for (int q = 0; q < 16; q++) {
            float eA = esm[tokA * HIDC + q * 32 + lane];
            float eB = esm[tokB * HIDC + q * 32 + lane];
#pragma unroll
            for (int t = 0; t < 5; t++) {
                sA[t] += eA * wreg[t][q];
                sB[t] += eB * wreg[t][q];
            }
        }
#pragma unroll
        for (int t = 0; t < 5; t++) {
#pragma unroll
            for (int off = 16; off > 0; off >>= 1) {
                sA[t] += __shfl_xor_sync(0xffffffffu, sA[t], off);
                sB[t] += __shfl_xor_sync(0xffffffffu, sB[t], off);
            }
        }
        if (lane == 0) {
#pragma unroll
            for (int t = 0; t < 5; t++) {
                d_feats[(tok0 + tokA) * NTAG + tw * 5 + t] = sA[t] + bloc[t];
                d_feats[(tok0 + tokB) * NTAG + tw * 5 + t] = sB[t] + bloc[t];
            }
        }
    }
}

// ---------------- V1: per-chunk maxplus products (barrier-free, warp-per-column) ----------------
// 128 blocks x 640 threads (20 warps). Warp k owns column k of the chunk product;
// lane j holds trans row j in registers and the scalar P[j][k]. Columns of a
// max-plus product chain are independent -> zero block barriers in the main loop.
__global__ __launch_bounds__(640) void viterbi_chunk_prod(const float* __restrict__ trans) {
    __shared__ float fsm[CLEN * NTAG];
    __shared__ float trs[NTAG * NTAG];
    int c = blockIdx.x, tid = threadIdx.x;
    int wk = tid >> 5, lane = tid & 31;   // wk = column k (0..19)
    for (int i = tid; i < CLEN * NTAG; i += 640) fsm[i] = d_feats[c * CLEN * NTAG + i];
    for (int i = tid; i < NTAG * NTAG; i += 640) trs[i] = trans[i];
    __syncthreads();

    // lane j: trans row j in registers
    float tr[NTAG];
#pragma unroll
    for (int m = 0; m < NTAG; m++) tr[m] = (lane < NTAG) ? trs[lane * NTAG + m] : -1e30f;

    // t=0: P[j][k] = trans[j][k] + feat[0][j]
    float P = (lane < NTAG) ? (trs[lane * NTAG + wk] + fsm[lane]) : -1e30f;

    for (int t = 1; t < CLEN; t++) {
        float v = -1e30f;
#pragma unroll
        for (int m = 0; m < NTAG; m++) {
            float pm = __shfl_sync(0xffffffffu, P, m);
            v = fmaxf(v, tr[m] + pm);
        }
        float f = (lane < NTAG) ? fsm[t * NTAG + lane] : 0.f;
        P = v + f;
    }
    if (lane < NTAG) d_P[c * NTAG * NTAG + lane * NTAG + wk] = P;
}

// ---------------- V2: sequential scan with prefetch ----------------
__global__ void viterbi_scan() {
    __shared__ float Ps[NTAG * NTAG];
    __shared__ float fvsm[NTAG];
    int lane = threadIdx.x;
    float cur[13], nx[13];
#pragma unroll
    for (int t = 0; t < 13; t++) {
        int i = lane + 32 * t;
        cur[t] = (i < NTAG * NTAG) ? d_P[i] : 0.f;
    }
    float fv = (lane == 18) ? 0.f : NEGV;
    for (int c = 0; c < NCHUNK; c++) {
#pragma unroll
        for (int t = 0; t < 13; t++) {
            int i = lane + 32 * t;
            if (i < NTAG * NTAG) Ps[i] = cur[t];
        }
        if (lane < NTAG) { d_fvs[c * NTAG + lane] = fv; fvsm[lane] = fv; }
        __syncwarp();
        if (c + 1 < NCHUNK) {
#pragma unroll
            for (int t = 0; t < 13; t++) {
                int i = lane + 32 * t;
                nx[t] = (i < NTAG * NTAG) ? d_P[(c + 1) * NTAG * NTAG + i] : 0.f;
            }
        }
        if (lane < NTAG) {
            float nf = -1e30f;
#pragma unroll
            for (int k = 0; k < NTAG; k++) nf = fmaxf(nf, Ps[lane * NTAG + k] + fvsm[k]);
            fv = nf;
        }
        __syncwarp();
#pragma unroll
        for (int t = 0; t < 13; t++) cur[t] = nx[t];
    }
}

// ---------------- V3: per-chunk forward + backpointers + chunk table (merged) ----------------
__global__ void viterbi_forward(const float* __restrict__ trans) {
    __shared__ float fsm[CLEN * NTAG];
    __shared__ unsigned char bsm[CLEN * NTAG];
    int c = blockIdx.x, lane = threadIdx.x;
    for (int i = lane; i < CLEN * NTAG; i += 32) fsm[i] = d_feats[c * CLEN * NTAG + i];
    __syncwarp();
    bool act = lane < NTAG;
    float tr[NTAG];
    if (act) {
#pragma unroll
        for (int m = 0; m < NTAG; m++) tr[m] = trans[lane * NTAG + m];
    }
    float fv = act ? d_fvs[c * NTAG + lane] : -1e30f;
    for (int t = 0; t < CLEN; t++) {
        float best = -1e30f;
        int bi = 0;
#pragma unroll
        for (int k = 0; k < NTAG; k++) {
            float v = __shfl_sync(0xffffffffu, fv, k);
            if (act) {
                v += tr[k];
                if (v > best) { best = v; bi = k; }
            }
        }
        if (act) {
            bsm[t * NTAG + lane] = (unsigned char)bi;
            fv = best + fsm[t * NTAG + lane];
        }
    }
    if (c == NCHUNK - 1 && act) d_finalfv[lane] = fv;
    __syncwarp();
    uint4* dst = (uint4*)(d_bps + c * CLEN * NTAG);
    const uint4* srcv = (const uint4*)bsm;
    for (int i = lane; i < (CLEN * NTAG) / 16; i += 32) dst[i] = srcv[i];
    if (act) {
        int x = lane;
        for (int t = CLEN - 1; t >= 0; t--) x = bsm[t * NTAG + x];
        d_Wc[c * NTAG + lane] = (unsigned char)x;
    }
}

// ---------------- B2: terminal argmax + boundary scan ----------------
__global__ void terminal_and_scan(const float* __restrict__ trans, float* __restrict__ out) {
    __shared__ unsigned char Wsm[NCHUNK * NTAG];
    int lane = threadIdx.x;
    const uint4* src = (const uint4*)d_Wc;
    for (int i = lane; i < (NCHUNK * NTAG) / 16; i += 32) ((uint4*)Wsm)[i] = src[i];
    float term = (lane < NTAG) ? d_finalfv[lane] + trans[19 * NTAG + lane] : -1e30f;
    __syncwarp();
    float best = -1e30f;
    int bi = 0;
#pragma unroll
    for (int k = 0; k < NTAG; k++) {
        float v = __shfl_sync(0xffffffffu, term, k);
        if (v > best) { best = v; bi = k; }
    }
    if (lane == 0) {
        out[0] = best;
        int r = bi;
        d_r[NCHUNK - 1] = (unsigned char)r;
        for (int c = NCHUNK - 1; c >= 1; c--) {
            r = Wsm[c * NTAG + r];
            d_r[c - 1] = (unsigned char)r;
        }
    }
}

// ---------------- B3: path emission ----------------
__global__ void backtrack_emit(float* __restrict__ out) {
    __shared__ unsigned char b[CLEN * NTAG];
    int c = blockIdx.x, lane = threadIdx.x;
    const uint4* src = (const uint4*)(d_bps + c * CLEN * NTAG);
    uint4* dstv = (uint4*)b;
    for (int i = lane; i < (CLEN * NTAG) / 16; i += 32) dstv[i] = src[i];
    __syncwarp();
    if (lane == 0) {
        int x = d_r[c];
        float* o = out + 1 + c * CLEN;
        for (int t = CLEN - 1; t >= 0; t--) {
            o[t] = (float)x;
            x = b[t * NTAG + x];
        }
    }
}

// ---------------- launch ----------------
extern "C" void kernel_launch(void* const* d_in, const int* in_sizes, int n_in,
                              void* d_out, int out_size) {
    const float* x      = (const float*)d_in[0];
    const float* w_ih_f = (const float*)d_in[1];
    const float* b_ih_f = (const float*)d_in[3];
    const float* b_hh_f = (const float*)d_in[4];
    const float* w_ih_b = (const float*)d_in[5];
    const float* b_ih_b = (const float*)d_in[7];
    const float* b_hh_b = (const float*)d_in[8];
    const float* w_tag  = (const float*)d_in[9];
    const float* b_tag  = (const float*)d_in[10];
    const float* trans  = (const float*)d_in[11];
    float* out = (float*)d_out;

    cudaFuncSetAttribute(gemm_fused, cudaFuncAttributeMaxDynamicSharedMemorySize, GSMEM);
    cudaFuncSetAttribute(feats_kernel, cudaFuncAttributeMaxDynamicSharedMemorySize,
                         FT_TOK * HIDC * (int)sizeof(float));

    prep_kernel<<<XBLK + WBLK, 256>>>(x, w_ih_f, w_ih_b, b_ih_f, b_hh_f, b_ih_b, b_hh_b);

    dim3 ggrid(NPACK / 96, NTOK / 128);
    gemm_fused<<<ggrid, 256, GSMEM>>>();

    feats_kernel<<<NTOK / FT_TOK, 256, FT_TOK * HIDC * sizeof(float)>>>(w_tag, b_tag);

    viterbi_chunk_prod<<<NCHUNK, 640>>>(trans);
    viterbi_scan<<<1, 32>>>();
    viterbi_forward<<<NCHUNK, 32>>>(trans);
    terminal_and_scan<<<1, 32>>>(trans, out);
    backtrack_emit<<<NCHUNK, 32>>>(out);
}